// round 1
// baseline (speedup 1.0000x reference)
#include <cuda_runtime.h>

// Problem constants (fixed by setup_inputs)
#define CC    120
#define BB    4096
#define PAIRS (CC * BB)          // 491520
#define GRID  1024
#define BLOCK 256
#define NGROUPS ((GRID * BLOCK) / 8)   // 32768 groups of 8 lanes
#define ITERS (PAIRS / NGROUPS)        // exactly 15 — uniform trip count
#define EPSF  1e-5f

// Accumulate the 6 antisymmetric components d_ki += w[i]*x[k] - w[k]*x[i]
// (w components indexed by k, x components indexed by i)
__device__ __forceinline__ void antisym_acc(const float4 w, const float4 x, float d[6]) {
    d[0] += w.y * x.x - w.x * x.y;   // (k=0,i=1)
    d[1] += w.z * x.x - w.x * x.z;   // (0,2)
    d[2] += w.w * x.x - w.x * x.w;   // (0,3)
    d[3] += w.z * x.y - w.y * x.z;   // (1,2)
    d[4] += w.w * x.y - w.y * x.w;   // (1,3)
    d[5] += w.w * x.z - w.z * x.w;   // (2,3)
}

__device__ __forceinline__ float sq6(const float d[6]) {
    return d[0]*d[0] + d[1]*d[1] + d[2]*d[2] + d[3]*d[3] + d[4]*d[4] + d[5]*d[5];
}

__global__ void __launch_bounds__(BLOCK)
ttfc_norm_kernel(const float4* __restrict__ in0,    // [C,B,1,8,4]   f4 idx: p*8 + s
                 const float4* __restrict__ in12,   // [2,C,B,4,8,4] f4 idx: (g*C*B + p)*32 + j*8 + s
                 const float4* __restrict__ w0,     // [1,8,4]       f4 idx: s
                 const float4* __restrict__ w12,    // [2,4,8,4]     f4 idx: (g*4+j)*8 + s
                 float* __restrict__ out)           // [B,C]
{
    const int tid = blockIdx.x * BLOCK + threadIdx.x;
    const int s   = tid & 7;        // slice lane within the 8-lane group
    const int g0  = tid >> 3;       // group id == first pair index

    // ---- preload the s-slice of the weights into registers (once) ----
    const float4 w0r = __ldg(&w0[s]);
    float4 w12r[2][4];
#pragma unroll
    for (int g = 0; g < 2; g++)
#pragma unroll
        for (int j = 0; j < 4; j++)
            w12r[g][j] = __ldg(&w12[(g * 4 + j) * 8 + s]);

    int p = g0;
#pragma unroll 1
    for (int it = 0; it < ITERS; it++, p += NGROUPS) {
        const int b = p & (BB - 1);
        const int c = p >> 12;          // p / BB, BB = 4096

        // ---- front-batched streaming loads: 9 x LDG.128 per lane ----
        // Each load is a fully-coalesced 128B line across the 8-lane group.
        const float4 x0 = __ldcs(&in0[p * 8 + s]);
        const int base0 = p * 32 + s;              // g = 0
        const int base1 = (CC * BB + p) * 32 + s;  // g = 1
        float4 xA[4], xB[4];
#pragma unroll
        for (int j = 0; j < 4; j++) {
            xA[j] = __ldcs(&in12[base0 + j * 8]);
            xB[j] = __ldcs(&in12[base1 + j * 8]);
        }

        // constant term: 3 cells (core0 + two core12 g's) x 16*eps^2 each
        float acc = 48.0f * (EPSF * EPSF);

        // ---- core0: single-j outer product ----
        {
            float d[6] = {0.f, 0.f, 0.f, 0.f, 0.f, 0.f};
            antisym_acc(w0r, x0, d);
            acc += 0.5f * sq6(d);
        }
        // ---- core12, g = 0 ----
        {
            float d[6] = {0.f, 0.f, 0.f, 0.f, 0.f, 0.f};
#pragma unroll
            for (int j = 0; j < 4; j++) antisym_acc(w12r[0][j], xA[j], d);
            acc += 0.5f * sq6(d);
        }
        // ---- core12, g = 1 ----
        {
            float d[6] = {0.f, 0.f, 0.f, 0.f, 0.f, 0.f};
#pragma unroll
            for (int j = 0; j < 4; j++) antisym_acc(w12r[1][j], xB[j], d);
            acc += 0.5f * sq6(d);
        }

        // ---- reduce over the 8 s-lanes (uniform trips -> full mask safe) ----
        acc += __shfl_xor_sync(0xFFFFFFFFu, acc, 1);
        acc += __shfl_xor_sync(0xFFFFFFFFu, acc, 2);
        acc += __shfl_xor_sync(0xFFFFFFFFu, acc, 4);

        if (s == 0) out[b * CC + c] = sqrtf(acc + EPSF);
    }
}

extern "C" void kernel_launch(void* const* d_in, const int* in_sizes, int n_in,
                              void* d_out, int out_size) {
    const float4* in0  = (const float4*)d_in[0];   // in_core0
    const float4* in12 = (const float4*)d_in[1];   // in_core12
    const float4* w0   = (const float4*)d_in[2];   // w_core0
    const float4* w12  = (const float4*)d_in[3];   // w_core12
    float* out = (float*)d_out;

    ttfc_norm_kernel<<<GRID, BLOCK>>>(in0, in12, w0, w12, out);
}

// round 2
// speedup vs baseline: 1.2886x; 1.2886x over previous
#include <cuda_runtime.h>

#define CC     120
#define BB     4096
#define PAIRS  (CC * BB)            // 491520
#define UNITS  (3 * PAIRS)          // 1474560 work units (class 0: core0, 1/2: core12 g)
#define BLOCK  256
#define GRID1  888                  // 148 SMs x 6 CTAs -> exactly one wave
#define NGROUPS1 (GRID1 * BLOCK / 8)            // 28416 eight-lane groups
#define TRIPS  ((UNITS + NGROUPS1 - 1) / NGROUPS1)  // 52 (uniform for all threads)
#define EPSF   1e-5f

// per-(class,b,c) partial sums; static device scratch (no allocation)
__device__ float4 g_scratch4[UNITS / 4];

// Unhoistable global load for weights (keeps them out of the live register set;
// 1.1KB of weights stays resident in L1 after first touch).
__device__ __forceinline__ float4 ldw(const float4* p) {
    float4 r;
    asm volatile("ld.global.nc.v4.f32 {%0,%1,%2,%3}, [%4];"
                 : "=f"(r.x), "=f"(r.y), "=f"(r.z), "=f"(r.w) : "l"(p));
    return r;
}

// d_ki += w[i]*x[k] - w[k]*x[i] for the 6 antisymmetric pairs
__device__ __forceinline__ void antisym_acc(const float4 w, const float4 x, float d[6]) {
    d[0] += w.y * x.x - w.x * x.y;
    d[1] += w.z * x.x - w.x * x.z;
    d[2] += w.w * x.x - w.x * x.w;
    d[3] += w.z * x.y - w.y * x.z;
    d[4] += w.w * x.y - w.y * x.w;
    d[5] += w.w * x.z - w.z * x.w;
}

__device__ __forceinline__ float sq6(const float d[6]) {
    return d[0]*d[0] + d[1]*d[1] + d[2]*d[2] + d[3]*d[3] + d[4]*d[4] + d[5]*d[5];
}

__global__ void __launch_bounds__(BLOCK, 6)
ttfc_partials_kernel(const float4* __restrict__ in0,   // [C,B,1,8,4]
                     const float4* __restrict__ in12,  // [2,C,B,4,8,4]
                     const float4* __restrict__ w0,    // [1,8,4]
                     const float4* __restrict__ w12)   // [2,4,8,4]
{
    float* scratch = (float*)g_scratch4;
    const int tid = blockIdx.x * BLOCK + threadIdx.x;
    const int s   = tid & 7;
    unsigned u = (unsigned)(tid >> 3);

#pragma unroll 1
    for (int t = 0; t < TRIPS; t++, u += NGROUPS1) {
        const unsigned uc = u < (UNITS - 1) ? u : (UNITS - 1);   // clamp: uniform trips
        const int k1  = uc >= (unsigned)PAIRS;
        const int k2  = uc >= (unsigned)(2 * PAIRS);
        const int cls = k1 + k2;                 // 0: core0, 1/2: core12 g=cls-1
        const int p   = (int)uc - cls * PAIRS;
        const int b   = p & (BB - 1);
        const int c   = p >> 12;

        float acc;
        float d[6] = {0.f, 0.f, 0.f, 0.f, 0.f, 0.f};
        if (cls == 0) {
            const float4 x = __ldcs(&in0[p * 8 + s]);      // 1 coalesced 128B line / group
            antisym_acc(ldw(&w0[s]), x, d);
            acc = 0.5f * sq6(d);
        } else {
            const int g    = cls - 1;
            const int base = (g * PAIRS + p) * 32 + s;
            // front-batched streaming loads: 4 x LDG.128, each a full 128B line / group
            float4 x0 = __ldcs(&in12[base + 0]);
            float4 x1 = __ldcs(&in12[base + 8]);
            float4 x2 = __ldcs(&in12[base + 16]);
            float4 x3 = __ldcs(&in12[base + 24]);
            const float4* wg = &w12[g * 32 + s];
            antisym_acc(ldw(wg + 0),  x0, d);
            antisym_acc(ldw(wg + 8),  x1, d);
            antisym_acc(ldw(wg + 16), x2, d);
            antisym_acc(ldw(wg + 24), x3, d);
            acc = 0.5f * sq6(d);
        }

        // reduce over the 8 s-lanes (all 32 lanes converged here, uniform trips)
        acc += __shfl_xor_sync(0xFFFFFFFFu, acc, 1);
        acc += __shfl_xor_sync(0xFFFFFFFFu, acc, 2);
        acc += __shfl_xor_sync(0xFFFFFFFFu, acc, 4);

        if (s == 0 && u < (unsigned)UNITS)
            scratch[cls * PAIRS + b * CC + c] = acc;
    }
}

// out[o] = sqrt(sum of the 3 class partials + 24*16*eps^2 + eps)
__global__ void __launch_bounds__(BLOCK)
ttfc_finish_kernel(float* __restrict__ out)
{
    const float4* sc = (const float4*)g_scratch4;
    const int i = blockIdx.x * BLOCK + threadIdx.x;       // 122880 threads, exact
    const float K = (float)(384.0 * 1e-10 + 1e-5);        // 384*eps^2 + eps

    float4 a = sc[i];
    float4 b = sc[i + PAIRS / 4];
    float4 c = sc[i + 2 * (PAIRS / 4)];
    float4 r;
    r.x = sqrtf(a.x + b.x + c.x + K);
    r.y = sqrtf(a.y + b.y + c.y + K);
    r.z = sqrtf(a.z + b.z + c.z + K);
    r.w = sqrtf(a.w + b.w + c.w + K);
    ((float4*)out)[i] = r;
}

extern "C" void kernel_launch(void* const* d_in, const int* in_sizes, int n_in,
                              void* d_out, int out_size) {
    const float4* in0  = (const float4*)d_in[0];
    const float4* in12 = (const float4*)d_in[1];
    const float4* w0   = (const float4*)d_in[2];
    const float4* w12  = (const float4*)d_in[3];
    float* out = (float*)d_out;

    ttfc_partials_kernel<<<GRID1, BLOCK>>>(in0, in12, w0, w12);
    ttfc_finish_kernel<<<PAIRS / 4 / BLOCK, BLOCK>>>(out);   // 480 CTAs
}

// round 3
// speedup vs baseline: 1.4243x; 1.1053x over previous
#include <cuda_runtime.h>

#define CC     120
#define BB     4096
#define PAIRS  (CC * BB)                 // 491520
#define BLOCK  256
#define GRID   592                       // 148 SMs x 4 CTAs -> exactly one wave
#define NGROUPS (GRID * BLOCK / 8)       // 18944 eight-lane groups
#define TRIPS  ((PAIRS + NGROUPS - 1) / NGROUPS)   // 26 (uniform for all threads)
#define EPSF   1e-5f

// Unhoistable weight load: keeps weights out of the persistent register set.
// 1.1 KB of weights lives in L1 after first touch (~L1-hit latency thereafter).
__device__ __forceinline__ float4 ldw(const float4* p) {
    float4 r;
    asm volatile("ld.global.nc.v4.f32 {%0,%1,%2,%3}, [%4];"
                 : "=f"(r.x), "=f"(r.y), "=f"(r.z), "=f"(r.w) : "l"(p));
    return r;
}

// d_ki += w[i]*x[k] - w[k]*x[i] for the 6 antisymmetric (k<i) pairs
__device__ __forceinline__ void antisym_acc(const float4 w, const float4 x, float d[6]) {
    d[0] += w.y * x.x - w.x * x.y;
    d[1] += w.z * x.x - w.x * x.z;
    d[2] += w.w * x.x - w.x * x.w;
    d[3] += w.z * x.y - w.y * x.z;
    d[4] += w.w * x.y - w.y * x.w;
    d[5] += w.w * x.z - w.z * x.w;
}

__device__ __forceinline__ float sq6(const float d[6]) {
    return d[0]*d[0] + d[1]*d[1] + d[2]*d[2] + d[3]*d[3] + d[4]*d[4] + d[5]*d[5];
}

__global__ void __launch_bounds__(BLOCK, 4)
ttfc_fused_kernel(const float4* __restrict__ in0,   // [C,B,1,8,4]   f4: p*8 + s
                  const float4* __restrict__ in12,  // [2,C,B,4,8,4] f4: (g*PAIRS+p)*32 + j*8 + s
                  const float4* __restrict__ w0,    // [1,8,4]       f4: s
                  const float4* __restrict__ w12,   // [2,4,8,4]     f4: (g*4+j)*8 + s
                  float* __restrict__ out)          // [B,C]
{
    const int tid = blockIdx.x * BLOCK + threadIdx.x;
    const int s   = tid & 7;
    unsigned u = (unsigned)(tid >> 3);

#pragma unroll 1
    for (int t = 0; t < TRIPS; t++, u += NGROUPS) {
        const int p = (u < (unsigned)PAIRS) ? (int)u : (PAIRS - 1);  // clamp: uniform trips
        const int b = p & (BB - 1);
        const int c = p >> 12;

        // ---- front-batched streaming loads: 9 x LDG.128 per lane,
        //      each a fully-coalesced 128B line across the 8-lane group ----
        const float4 x0 = __ldcs(&in0[p * 8 + s]);
        const int baseA = p * 32 + s;              // core12, g = 0
        const int baseB = (PAIRS + p) * 32 + s;    // core12, g = 1
        float4 xA0 = __ldcs(&in12[baseA + 0]);
        float4 xA1 = __ldcs(&in12[baseA + 8]);
        float4 xA2 = __ldcs(&in12[baseA + 16]);
        float4 xA3 = __ldcs(&in12[baseA + 24]);
        float4 xB0 = __ldcs(&in12[baseB + 0]);
        float4 xB1 = __ldcs(&in12[baseB + 8]);
        float4 xB2 = __ldcs(&in12[baseB + 16]);
        float4 xB3 = __ldcs(&in12[baseB + 24]);

        // 3 cells for this lane's s (core0 + two core12 g's): 3 * 16 * eps^2
        float acc = 48.0f * (EPSF * EPSF);

        {   // core0
            float d[6] = {0.f, 0.f, 0.f, 0.f, 0.f, 0.f};
            antisym_acc(ldw(&w0[s]), x0, d);
            acc += 0.5f * sq6(d);
        }
        {   // core12, g = 0
            float d[6] = {0.f, 0.f, 0.f, 0.f, 0.f, 0.f};
            const float4* wg = &w12[s];
            antisym_acc(ldw(wg + 0),  xA0, d);
            antisym_acc(ldw(wg + 8),  xA1, d);
            antisym_acc(ldw(wg + 16), xA2, d);
            antisym_acc(ldw(wg + 24), xA3, d);
            acc += 0.5f * sq6(d);
        }
        {   // core12, g = 1
            float d[6] = {0.f, 0.f, 0.f, 0.f, 0.f, 0.f};
            const float4* wg = &w12[32 + s];
            antisym_acc(ldw(wg + 0),  xB0, d);
            antisym_acc(ldw(wg + 8),  xB1, d);
            antisym_acc(ldw(wg + 16), xB2, d);
            antisym_acc(ldw(wg + 24), xB3, d);
            acc += 0.5f * sq6(d);
        }

        // ---- reduce over the 8 s-lanes (uniform trips -> full mask safe) ----
        acc += __shfl_xor_sync(0xFFFFFFFFu, acc, 1);
        acc += __shfl_xor_sync(0xFFFFFFFFu, acc, 2);
        acc += __shfl_xor_sync(0xFFFFFFFFu, acc, 4);

        // output sectors coalesce in L2 (2MB total fits), write back as full lines
        if (s == 0 && u < (unsigned)PAIRS)
            out[b * CC + c] = sqrtf(acc + EPSF);
    }
}

extern "C" void kernel_launch(void* const* d_in, const int* in_sizes, int n_in,
                              void* d_out, int out_size) {
    const float4* in0  = (const float4*)d_in[0];
    const float4* in12 = (const float4*)d_in[1];
    const float4* w0   = (const float4*)d_in[2];
    const float4* w12  = (const float4*)d_in[3];
    float* out = (float*)d_out;

    ttfc_fused_kernel<<<GRID, BLOCK>>>(in0, in12, w0, w12, out);
}